// round 14
// baseline (speedup 1.0000x reference)
#include <cuda_runtime.h>
#include <math.h>
#include <stdint.h>

#define BATCH 16
#define CHAN  256
#define NPIX  4096
#define KSPLIT 8
#define KCH   (NPIX / KSPLIT)   // 512

typedef unsigned long long ull;

// Scratch (allocation-free: __device__ globals)
__device__ float g_epart[(size_t)KSPLIT * 3 * BATCH * CHAN * CHAN];  // 100.7 MB
__device__ float g_energy[3u * BATCH * CHAN * CHAN];                 // 12.6 MB
__device__ float g_attn[(unsigned)BATCH * CHAN * CHAN];
__device__ float g_M[(unsigned)BATCH * CHAN * CHAN];

#define EPART_STRIDE ((size_t)3 * BATCH * CHAN * CHAN)   // floats per k-partial

// ---- packed f32x2 helpers ---------------------------------------------------
__device__ __forceinline__ ull bcast2(float v) {
    ull r; asm("mov.b64 %0, {%1, %1};" : "=l"(r) : "f"(v)); return r;
}
__device__ __forceinline__ void fma2(ull& d, ull a, ull b) {
    asm("fma.rn.f32x2 %0, %1, %2, %0;" : "+l"(d) : "l"(a), "l"(b));
}
__device__ __forceinline__ float2 unpack2(ull v) {
    float2 r; asm("mov.b64 {%0, %1}, %2;" : "=f"(r.x), "=f"(r.y) : "l"(v)); return r;
}

// ---------------------------------------------------------------------------
// Kernel 1: partial energy, split-K=8. Block tile 128x128x16, 128 threads,
// 16x8 micro-tile (2.67 FLOP/LDS-byte), double-buffered smem.
//   g_epart[kc][s][b][c][d] = sum_{n in chunk kc} x[b,c,n] * src_s[b,d,n]
// s=0 (x@x^T) symmetric: tile (1,0) skipped, tile (0,1) writes its mirror.
// ---------------------------------------------------------------------------
__global__ __launch_bounds__(128, 2)
void energy_kernel(const float* __restrict__ x, const float* __restrict__ y,
                   const float* __restrict__ z)
{
    constexpr int TK = 16, PA = 136;
    constexpr int NIT = KCH / TK;     // 32
    __shared__ float As[2][TK * PA];
    __shared__ float Bs[2][TK * PA];

    int id = blockIdx.x;
    int t      = id & 3;
    int kchunk = (id >> 2) & (KSPLIT - 1);
    int bs     = id >> 5;
    int b  = bs & 15;
    int s  = bs >> 4;
    if (s == 0 && t == 2) return;           // symmetric: mirror of tile (0,1)
    int cBase = (t >> 1) * 128;
    int dBase = (t & 1) * 128;
    int kStart = kchunk * KCH;

    const float* A = x + (size_t)b * (CHAN * NPIX);
    const float* S = (s == 0 ? x : (s == 1 ? y : z)) + (size_t)b * (CHAN * NPIX);

    int tid = threadIdx.x;
    int tx = tid & 15, ty = tid >> 4;       // ty: m-block 0..7, tx: n-quad

    const float* pA = A + (size_t)(cBase + tid) * NPIX + kStart;
    const float* pB = S + (size_t)(dBase + tid) * NPIX + kStart;

    float4 ra[4], rb[4];
    #pragma unroll
    for (int g = 0; g < 4; g++) {
        ra[g] = *(const float4*)(pA + g * 4);
        rb[g] = *(const float4*)(pB + g * 4);
    }
    {   // chunk 0 -> buf 0  (transpose to [k][m])
        float* a = As[0]; float* bsm = Bs[0];
        #pragma unroll
        for (int g = 0; g < 4; g++) {
            a[(g*4+0)*PA + tid] = ra[g].x;  a[(g*4+1)*PA + tid] = ra[g].y;
            a[(g*4+2)*PA + tid] = ra[g].z;  a[(g*4+3)*PA + tid] = ra[g].w;
            bsm[(g*4+0)*PA + tid] = rb[g].x;  bsm[(g*4+1)*PA + tid] = rb[g].y;
            bsm[(g*4+2)*PA + tid] = rb[g].z;  bsm[(g*4+3)*PA + tid] = rb[g].w;
        }
    }
    pA += TK; pB += TK;
    #pragma unroll
    for (int g = 0; g < 4; g++) {
        ra[g] = *(const float4*)(pA + g * 4);
        rb[g] = *(const float4*)(pB + g * 4);
    }

    ull acc2[8][8];
    #pragma unroll
    for (int i = 0; i < 8; i++)
        #pragma unroll
        for (int j = 0; j < 8; j++) acc2[i][j] = 0ull;

    for (int ch = 0; ch < NIT; ch++) {
        __syncthreads();
        int cur = ch & 1, nxt = cur ^ 1;

        if (ch + 1 < NIT) {
            float* a = As[nxt]; float* bsm = Bs[nxt];
            #pragma unroll
            for (int g = 0; g < 4; g++) {
                a[(g*4+0)*PA + tid] = ra[g].x;  a[(g*4+1)*PA + tid] = ra[g].y;
                a[(g*4+2)*PA + tid] = ra[g].z;  a[(g*4+3)*PA + tid] = ra[g].w;
                bsm[(g*4+0)*PA + tid] = rb[g].x;  bsm[(g*4+1)*PA + tid] = rb[g].y;
                bsm[(g*4+2)*PA + tid] = rb[g].z;  bsm[(g*4+3)*PA + tid] = rb[g].w;
            }
        }
        if (ch + 2 < NIT) {
            pA += TK; pB += TK;
            #pragma unroll
            for (int g = 0; g < 4; g++) {
                ra[g] = *(const float4*)(pA + g * 4);
                rb[g] = *(const float4*)(pB + g * 4);
            }
        }

        const float* a = As[cur]; const float* bsm = Bs[cur];
        #pragma unroll
        for (int k = 0; k < TK; k++) {
            ulonglong2 q0 = *(const ulonglong2*)&a[k*PA + ty*16];
            ulonglong2 q1 = *(const ulonglong2*)&a[k*PA + ty*16 + 4];
            ulonglong2 q2 = *(const ulonglong2*)&a[k*PA + ty*16 + 8];
            ulonglong2 q3 = *(const ulonglong2*)&a[k*PA + ty*16 + 12];
            ull aa[8] = {q0.x, q0.y, q1.x, q1.y, q2.x, q2.y, q3.x, q3.y};
            float4 b0 = *(const float4*)&bsm[k*PA + tx*4];
            float4 b1 = *(const float4*)&bsm[k*PA + 64 + tx*4];
            ull bb[8] = {bcast2(b0.x), bcast2(b0.y), bcast2(b0.z), bcast2(b0.w),
                         bcast2(b1.x), bcast2(b1.y), bcast2(b1.z), bcast2(b1.w)};
            #pragma unroll
            for (int i = 0; i < 8; i++)
                #pragma unroll
                for (int j = 0; j < 8; j++)
                    fma2(acc2[i][j], aa[i], bb[j]);
        }
    }

    float* E = g_epart + (size_t)kchunk * EPART_STRIDE +
               ((size_t)s * BATCH + b) * (CHAN * CHAN);
    #pragma unroll
    for (int r = 0; r < 16; r++) {
        int row = cBase + ty * 16 + r;
        float v[8];
        #pragma unroll
        for (int n = 0; n < 8; n++) {
            float2 u = unpack2(acc2[r >> 1][n]);
            v[n] = (r & 1) ? u.y : u.x;
        }
        *(float4*)&E[(size_t)row * CHAN + dBase + tx*4] =
            make_float4(v[0], v[1], v[2], v[3]);
        *(float4*)&E[(size_t)row * CHAN + dBase + 64 + tx*4] =
            make_float4(v[4], v[5], v[6], v[7]);
    }

    if (s == 0 && t == 1) {   // mirror write (symmetric)
        #pragma unroll
        for (int n = 0; n < 8; n++) {
            int nGlob = dBase + ((n < 4) ? (tx*4 + n) : (64 + tx*4 + n - 4));
            float2 u0 = unpack2(acc2[0][n]), u1 = unpack2(acc2[1][n]);
            float2 u2 = unpack2(acc2[2][n]), u3 = unpack2(acc2[3][n]);
            float2 u4 = unpack2(acc2[4][n]), u5 = unpack2(acc2[5][n]);
            float2 u6 = unpack2(acc2[6][n]), u7 = unpack2(acc2[7][n]);
            float* dst = E + (size_t)nGlob * CHAN + cBase + ty * 16;
            *(float4*)(dst + 0)  = make_float4(u0.x, u0.y, u1.x, u1.y);
            *(float4*)(dst + 4)  = make_float4(u2.x, u2.y, u3.x, u3.y);
            *(float4*)(dst + 8)  = make_float4(u4.x, u4.y, u5.x, u5.y);
            *(float4*)(dst + 12) = make_float4(u6.x, u6.y, u7.x, u7.y);
        }
    }
}

// ---------------------------------------------------------------------------
// Kernel 1b: streaming reduction of KSPLIT partials -> g_energy.
// Grid-stride float4; 8-way MLP per output, pure BW.
// ---------------------------------------------------------------------------
__global__ __launch_bounds__(256)
void reduce_kernel()
{
    const size_t nVec = EPART_STRIDE / 4;           // float4 count
    const float4* in  = (const float4*)g_epart;
    float4* out = (float4*)g_energy;
    size_t step = (size_t)gridDim.x * blockDim.x;
    for (size_t i = (size_t)blockIdx.x * blockDim.x + threadIdx.x;
         i < nVec; i += step) {
        float4 acc = in[i];
        #pragma unroll
        for (int p = 1; p < KSPLIT; p++) {
            float4 v = in[(size_t)p * (EPART_STRIDE / 4) + i];
            acc.x += v.x; acc.y += v.y; acc.z += v.z; acc.w += v.w;
        }
        out[i] = acc;
    }
}

// ---------------------------------------------------------------------------
// Kernel 2: attn[b][c][:] = sum_s softmax(rowmax(E_s) - E_s).
// One warp per (b,c) row, reading the reduced g_energy.
// ---------------------------------------------------------------------------
__global__ __launch_bounds__(256)
void softmax_sum_kernel()
{
    int gwarp = (blockIdx.x * blockDim.x + threadIdx.x) >> 5;
    int lane  = threadIdx.x & 31;

    float acc[8];
    #pragma unroll
    for (int i = 0; i < 8; i++) acc[i] = 0.f;

    #pragma unroll
    for (int s = 0; s < 3; s++) {
        const float* row = g_energy + ((size_t)s * BATCH * CHAN + gwarp) * CHAN;
        float4 e0 = *(const float4*)&row[lane * 8];
        float4 e1 = *(const float4*)&row[lane * 8 + 4];
        float e[8] = {e0.x, e0.y, e0.z, e0.w, e1.x, e1.y, e1.z, e1.w};

        float m1 = e[0];
        #pragma unroll
        for (int i = 1; i < 8; i++) m1 = fmaxf(m1, e[i]);
        #pragma unroll
        for (int o = 16; o > 0; o >>= 1)
            m1 = fmaxf(m1, __shfl_xor_sync(0xffffffffu, m1, o));

        float v[8], m2 = -3.402823466e38f;
        #pragma unroll
        for (int i = 0; i < 8; i++) { v[i] = m1 - e[i]; m2 = fmaxf(m2, v[i]); }
        #pragma unroll
        for (int o = 16; o > 0; o >>= 1)
            m2 = fmaxf(m2, __shfl_xor_sync(0xffffffffu, m2, o));

        float p8[8], Ssum = 0.f;
        #pragma unroll
        for (int i = 0; i < 8; i++) { p8[i] = expf(v[i] - m2); Ssum += p8[i]; }
        #pragma unroll
        for (int o = 16; o > 0; o >>= 1)
            Ssum += __shfl_xor_sync(0xffffffffu, Ssum, o);

        float inv = 1.f / Ssum;
        #pragma unroll
        for (int i = 0; i < 8; i++) acc[i] += p8[i] * inv;
    }

    float* out = g_attn + (size_t)gwarp * CHAN + lane * 8;
    *(float4*)&out[0] = make_float4(acc[0], acc[1], acc[2], acc[3]);
    *(float4*)&out[4] = make_float4(acc[4], acc[5], acc[6], acc[7]);
}

// ---------------------------------------------------------------------------
// Kernels 3/4: TN GEMM, C = A @ B, K=256. Block tile 128x128x16, 128 threads,
// 16x8 micro-tile, double-buffered smem.
//   FINAL=false: O = gamma * acc
//   FINAL=true : O = acc + gamma*bias[m] + resid
// ---------------------------------------------------------------------------
template<int NCOLS, bool FINAL>
__global__ __launch_bounds__(128, 2)
void gemm_tn(const float* __restrict__ Ab, long aStride,
             const float* __restrict__ Bb, long bStride,
             float* __restrict__ Ob,
             const float* __restrict__ bias,
             const float* __restrict__ gamma_p,
             const float* __restrict__ resid)
{
    constexpr int TK = 16, Kdim = 256, PA = 136;
    constexpr int NIT = Kdim / TK;   // 16
    constexpr int NT = NCOLS / 128;
    __shared__ float As[2][TK * PA];
    __shared__ float Bs[2][TK * 128];

    int id = blockIdx.x;
    int nt = id % NT; id /= NT;
    int mt = id & 1;
    int b  = id >> 1;
    int mBase = mt * 128, nBase = nt * 128;

    const float* A = Ab + (size_t)b * aStride;
    const float* B = Bb + (size_t)b * bStride;
    float* O = Ob + (size_t)b * ((size_t)CHAN * NCOLS);
    const float* R = FINAL ? (resid + (size_t)b * ((size_t)CHAN * NCOLS)) : nullptr;

    int tid = threadIdx.x;
    int tx = tid & 15, ty = tid >> 4;

    const float* pA = A + (size_t)(mBase + tid) * Kdim;
    int krB = tid >> 5, nvB = tid & 31;
    const float* pB = B + (size_t)krB * NCOLS + nBase + nvB * 4;

    float4 ra[4], rb[4];
    #pragma unroll
    for (int g = 0; g < 4; g++) {
        ra[g] = *(const float4*)(pA + g * 4);
        rb[g] = *(const float4*)(pB + (size_t)(g * 4) * NCOLS);
    }
    {
        float* a = As[0]; float* bsm = Bs[0];
        #pragma unroll
        for (int g = 0; g < 4; g++) {
            a[(g*4+0)*PA + tid] = ra[g].x;  a[(g*4+1)*PA + tid] = ra[g].y;
            a[(g*4+2)*PA + tid] = ra[g].z;  a[(g*4+3)*PA + tid] = ra[g].w;
            *(float4*)&bsm[(krB + g*4) * 128 + nvB * 4] = rb[g];
        }
    }
    pA += TK; pB += (size_t)TK * NCOLS;
    #pragma unroll
    for (int g = 0; g < 4; g++) {
        ra[g] = *(const float4*)(pA + g * 4);
        rb[g] = *(const float4*)(pB + (size_t)(g * 4) * NCOLS);
    }

    ull acc2[8][8];
    #pragma unroll
    for (int i = 0; i < 8; i++)
        #pragma unroll
        for (int j = 0; j < 8; j++) acc2[i][j] = 0ull;

    for (int ch = 0; ch < NIT; ch++) {
        __syncthreads();
        int cur = ch & 1, nxt = cur ^ 1;

        if (ch + 1 < NIT) {
            float* a = As[nxt]; float* bsm = Bs[nxt];
            #pragma unroll
            for (int g = 0; g < 4; g++) {
                a[(g*4+0)*PA + tid] = ra[g].x;  a[(g*4+1)*PA + tid] = ra[g].y;
                a[(g*4+2)*PA + tid] = ra[g].z;  a[(g*4+3)*PA + tid] = ra[g].w;
                *(float4*)&bsm[(krB + g*4) * 128 + nvB * 4] = rb[g];
            }
        }
        if (ch + 2 < NIT) {
            pA += TK; pB += (size_t)TK * NCOLS;
            #pragma unroll
            for (int g = 0; g < 4; g++) {
                ra[g] = *(const float4*)(pA + g * 4);
                rb[g] = *(const float4*)(pB + (size_t)(g * 4) * NCOLS);
            }
        }

        const float* a = As[cur]; const float* bsm = Bs[cur];
        #pragma unroll
        for (int k = 0; k < TK; k++) {
            ulonglong2 q0 = *(const ulonglong2*)&a[k*PA + ty*16];
            ulonglong2 q1 = *(const ulonglong2*)&a[k*PA + ty*16 + 4];
            ulonglong2 q2 = *(const ulonglong2*)&a[k*PA + ty*16 + 8];
            ulonglong2 q3 = *(const ulonglong2*)&a[k*PA + ty*16 + 12];
            ull aa[8] = {q0.x, q0.y, q1.x, q1.y, q2.x, q2.y, q3.x, q3.y};
            float4 b0 = *(const float4*)&bsm[k*128 + tx*4];
            float4 b1 = *(const float4*)&bsm[k*128 + 64 + tx*4];
            ull bb[8] = {bcast2(b0.x), bcast2(b0.y), bcast2(b0.z), bcast2(b0.w),
                         bcast2(b1.x), bcast2(b1.y), bcast2(b1.z), bcast2(b1.w)};
            #pragma unroll
            for (int i = 0; i < 8; i++)
                #pragma unroll
                for (int j = 0; j < 8; j++)
                    fma2(acc2[i][j], aa[i], bb[j]);
        }
    }

    float gamma = gamma_p[0];
    #pragma unroll
    for (int r = 0; r < 16; r++) {
        int row = mBase + ty * 16 + r;
        size_t base = (size_t)row * NCOLS + nBase + tx*4;
        float v[8];
        #pragma unroll
        for (int n = 0; n < 8; n++) {
            float2 u = unpack2(acc2[r >> 1][n]);
            v[n] = (r & 1) ? u.y : u.x;
        }
        if (FINAL) {
            float gb = gamma * bias[row];
            float4 r0 = *(const float4*)&R[base];
            float4 r1 = *(const float4*)&R[base + 64];
            *(float4*)&O[base] = make_float4(
                v[0] + gb + r0.x, v[1] + gb + r0.y,
                v[2] + gb + r0.z, v[3] + gb + r0.w);
            *(float4*)&O[base + 64] = make_float4(
                v[4] + gb + r1.x, v[5] + gb + r1.y,
                v[6] + gb + r1.z, v[7] + gb + r1.w);
        } else {
            *(float4*)&O[base] = make_float4(
                gamma*v[0], gamma*v[1], gamma*v[2], gamma*v[3]);
            *(float4*)&O[base + 64] = make_float4(
                gamma*v[4], gamma*v[5], gamma*v[6], gamma*v[7]);
        }
    }
}

// ---------------------------------------------------------------------------
extern "C" void kernel_launch(void* const* d_in, const int* in_sizes, int n_in,
                              void* d_out, int out_size)
{
    const float* x      = (const float*)d_in[0];
    const float* y      = (const float*)d_in[1];
    const float* z      = (const float*)d_in[2];
    const float* conv_w = (const float*)d_in[3];
    const float* conv_b = (const float*)d_in[4];
    const float* gamma  = (const float*)d_in[5];
    float* out = (float*)d_out;

    float *pAttn, *pM;
    cudaGetSymbolAddress((void**)&pAttn, g_attn);
    cudaGetSymbolAddress((void**)&pM, g_M);

    // 1) three energy GEMMs, split-K=8: 1536 CTAs (128 exit early via symmetry)
    energy_kernel<<<3 * BATCH * 4 * KSPLIT, 128>>>(x, y, z);
    // 1b) reduce 8 partials -> g_energy (pure streaming)
    reduce_kernel<<<592, 256>>>();
    // 2) softmax + sum over sources
    softmax_sum_kernel<<<BATCH * CHAN / 8, 256>>>();
    // 3) M_b = gamma * conv_w @ attn_b  (64 CTAs)
    gemm_tn<CHAN, false><<<BATCH * 2 * 2, 128>>>(
        conv_w, 0, pAttn, (long)CHAN * CHAN, pM, nullptr, gamma, nullptr);
    // 4) out = M_b @ x_b + gamma*conv_b + x  (1024 CTAs)
    gemm_tn<NPIX, true><<<BATCH * 2 * 32, 128>>>(
        pM, (long)CHAN * CHAN, x, (long)CHAN * NPIX, out, conv_b, gamma, x);
}

// round 16
// speedup vs baseline: 1.0756x; 1.0756x over previous
#include <cuda_runtime.h>
#include <math.h>
#include <stdint.h>

#define BATCH 16
#define CHAN  256
#define NPIX  4096
#define KSPLIT 5                 // uneven: 832 + 4x816

typedef unsigned long long ull;

// Scratch (allocation-free: __device__ globals)
__device__ float g_epart[(size_t)KSPLIT * 3 * BATCH * CHAN * CHAN];  // 63 MB
__device__ float g_attn[(unsigned)BATCH * CHAN * CHAN];
__device__ float g_Mp[4u * BATCH * CHAN * CHAN];                     // M partials
__device__ float g_M[(unsigned)BATCH * CHAN * CHAN];

#define EPART_STRIDE ((size_t)3 * BATCH * CHAN * CHAN)

// ---- packed f32x2 helpers ---------------------------------------------------
__device__ __forceinline__ ull bcast2(float v) {
    ull r; asm("mov.b64 %0, {%1, %1};" : "=l"(r) : "f"(v)); return r;
}
__device__ __forceinline__ void fma2(ull& d, ull a, ull b) {
    asm("fma.rn.f32x2 %0, %1, %2, %0;" : "+l"(d) : "l"(a), "l"(b));
}
__device__ __forceinline__ float2 unpack2(ull v) {
    float2 r; asm("mov.b64 {%0, %1}, %2;" : "=f"(r.x), "=f"(r.y) : "l"(v)); return r;
}

// ---------------------------------------------------------------------------
// Kernel 1: partial energy, split-K=5 (uneven). Block tile 128x128x16,
// 128 threads, 16x8 micro-tile, double-buffered smem. 960 CTAs -> 880 work
// units (s=0 symmetric tile skipped) = 2.97 waves at occ 2.
// ---------------------------------------------------------------------------
__global__ __launch_bounds__(128, 2)
void energy_kernel(const float* __restrict__ x, const float* __restrict__ y,
                   const float* __restrict__ z)
{
    constexpr int TK = 16, PA = 136;
    __shared__ float As[2][TK * PA];
    __shared__ float Bs[2][TK * PA];

    int id = blockIdx.x;
    int t  = id & 3;
    int r5 = id >> 2;            // 0..239
    int kchunk = r5 % 5;
    int bs     = r5 / 5;         // 0..47
    int b  = bs & 15;
    int s  = bs >> 4;
    if (s == 0 && t == 2) return;           // symmetric: mirror of tile (0,1)
    int cBase = (t >> 1) * 128;
    int dBase = (t & 1) * 128;
    int kStart = kchunk ? (16 + 816 * kchunk) : 0;
    int NIT    = kchunk ? 51 : 52;          // chunk len / 16

    const float* A = x + (size_t)b * (CHAN * NPIX);
    const float* S = (s == 0 ? x : (s == 1 ? y : z)) + (size_t)b * (CHAN * NPIX);

    int tid = threadIdx.x;
    int tx = tid & 15, ty = tid >> 4;

    const float* pA = A + (size_t)(cBase + tid) * NPIX + kStart;
    const float* pB = S + (size_t)(dBase + tid) * NPIX + kStart;

    float4 ra[4], rb[4];
    #pragma unroll
    for (int g = 0; g < 4; g++) {
        ra[g] = *(const float4*)(pA + g * 4);
        rb[g] = *(const float4*)(pB + g * 4);
    }
    {   // chunk 0 -> buf 0
        float* a = As[0]; float* bsm = Bs[0];
        #pragma unroll
        for (int g = 0; g < 4; g++) {
            a[(g*4+0)*PA + tid] = ra[g].x;  a[(g*4+1)*PA + tid] = ra[g].y;
            a[(g*4+2)*PA + tid] = ra[g].z;  a[(g*4+3)*PA + tid] = ra[g].w;
            bsm[(g*4+0)*PA + tid] = rb[g].x;  bsm[(g*4+1)*PA + tid] = rb[g].y;
            bsm[(g*4+2)*PA + tid] = rb[g].z;  bsm[(g*4+3)*PA + tid] = rb[g].w;
        }
    }
    pA += TK; pB += TK;
    #pragma unroll
    for (int g = 0; g < 4; g++) {
        ra[g] = *(const float4*)(pA + g * 4);
        rb[g] = *(const float4*)(pB + g * 4);
    }

    ull acc2[8][8];
    #pragma unroll
    for (int i = 0; i < 8; i++)
        #pragma unroll
        for (int j = 0; j < 8; j++) acc2[i][j] = 0ull;

    for (int ch = 0; ch < NIT; ch++) {
        __syncthreads();
        int cur = ch & 1, nxt = cur ^ 1;

        if (ch + 1 < NIT) {
            float* a = As[nxt]; float* bsm = Bs[nxt];
            #pragma unroll
            for (int g = 0; g < 4; g++) {
                a[(g*4+0)*PA + tid] = ra[g].x;  a[(g*4+1)*PA + tid] = ra[g].y;
                a[(g*4+2)*PA + tid] = ra[g].z;  a[(g*4+3)*PA + tid] = ra[g].w;
                bsm[(g*4+0)*PA + tid] = rb[g].x;  bsm[(g*4+1)*PA + tid] = rb[g].y;
                bsm[(g*4+2)*PA + tid] = rb[g].z;  bsm[(g*4+3)*PA + tid] = rb[g].w;
            }
        }
        if (ch + 2 < NIT) {
            pA += TK; pB += TK;
            #pragma unroll
            for (int g = 0; g < 4; g++) {
                ra[g] = *(const float4*)(pA + g * 4);
                rb[g] = *(const float4*)(pB + g * 4);
            }
        }

        const float* a = As[cur]; const float* bsm = Bs[cur];
        #pragma unroll
        for (int k = 0; k < TK; k++) {
            ulonglong2 q0 = *(const ulonglong2*)&a[k*PA + ty*16];
            ulonglong2 q1 = *(const ulonglong2*)&a[k*PA + ty*16 + 4];
            ulonglong2 q2 = *(const ulonglong2*)&a[k*PA + ty*16 + 8];
            ulonglong2 q3 = *(const ulonglong2*)&a[k*PA + ty*16 + 12];
            ull aa[8] = {q0.x, q0.y, q1.x, q1.y, q2.x, q2.y, q3.x, q3.y};
            float4 b0 = *(const float4*)&bsm[k*PA + tx*4];
            float4 b1 = *(const float4*)&bsm[k*PA + 64 + tx*4];
            ull bb[8] = {bcast2(b0.x), bcast2(b0.y), bcast2(b0.z), bcast2(b0.w),
                         bcast2(b1.x), bcast2(b1.y), bcast2(b1.z), bcast2(b1.w)};
            #pragma unroll
            for (int i = 0; i < 8; i++)
                #pragma unroll
                for (int j = 0; j < 8; j++)
                    fma2(acc2[i][j], aa[i], bb[j]);
        }
    }

    float* E = g_epart + (size_t)kchunk * EPART_STRIDE +
               ((size_t)s * BATCH + b) * (CHAN * CHAN);
    #pragma unroll
    for (int r = 0; r < 16; r++) {
        int row = cBase + ty * 16 + r;
        float v[8];
        #pragma unroll
        for (int n = 0; n < 8; n++) {
            float2 u = unpack2(acc2[r >> 1][n]);
            v[n] = (r & 1) ? u.y : u.x;
        }
        *(float4*)&E[(size_t)row * CHAN + dBase + tx*4] =
            make_float4(v[0], v[1], v[2], v[3]);
        *(float4*)&E[(size_t)row * CHAN + dBase + 64 + tx*4] =
            make_float4(v[4], v[5], v[6], v[7]);
    }

    if (s == 0 && t == 1) {   // mirror write (symmetric)
        #pragma unroll
        for (int n = 0; n < 8; n++) {
            int nGlob = dBase + ((n < 4) ? (tx*4 + n) : (64 + tx*4 + n - 4));
            float2 u0 = unpack2(acc2[0][n]), u1 = unpack2(acc2[1][n]);
            float2 u2 = unpack2(acc2[2][n]), u3 = unpack2(acc2[3][n]);
            float2 u4 = unpack2(acc2[4][n]), u5 = unpack2(acc2[5][n]);
            float2 u6 = unpack2(acc2[6][n]), u7 = unpack2(acc2[7][n]);
            float* dst = E + (size_t)nGlob * CHAN + cBase + ty * 16;
            *(float4*)(dst + 0)  = make_float4(u0.x, u0.y, u1.x, u1.y);
            *(float4*)(dst + 4)  = make_float4(u2.x, u2.y, u3.x, u3.y);
            *(float4*)(dst + 8)  = make_float4(u4.x, u4.y, u5.x, u5.y);
            *(float4*)(dst + 12) = make_float4(u6.x, u6.y, u7.x, u7.y);
        }
    }
}

// ---------------------------------------------------------------------------
// Kernel 2: attn[b][c][:] = sum_s softmax(rowmax(E_s) - E_s); E_s = sum of
// 5 partials, read directly. One warp per (b,c) row.
// ---------------------------------------------------------------------------
__global__ __launch_bounds__(256)
void softmax_sum_kernel()
{
    int gwarp = (blockIdx.x * blockDim.x + threadIdx.x) >> 5;
    int lane  = threadIdx.x & 31;

    float acc[8];
    #pragma unroll
    for (int i = 0; i < 8; i++) acc[i] = 0.f;

    #pragma unroll
    for (int s = 0; s < 3; s++) {
        float e[8];
        #pragma unroll
        for (int i = 0; i < 8; i++) e[i] = 0.f;
        #pragma unroll
        for (int p = 0; p < KSPLIT; p++) {
            const float* row = g_epart + (size_t)p * EPART_STRIDE +
                ((size_t)s * BATCH * CHAN + gwarp) * CHAN;
            float4 e0 = *(const float4*)&row[lane * 8];
            float4 e1 = *(const float4*)&row[lane * 8 + 4];
            e[0] += e0.x; e[1] += e0.y; e[2] += e0.z; e[3] += e0.w;
            e[4] += e1.x; e[5] += e1.y; e[6] += e1.z; e[7] += e1.w;
        }

        float m1 = e[0];
        #pragma unroll
        for (int i = 1; i < 8; i++) m1 = fmaxf(m1, e[i]);
        #pragma unroll
        for (int o = 16; o > 0; o >>= 1)
            m1 = fmaxf(m1, __shfl_xor_sync(0xffffffffu, m1, o));

        float v[8], m2 = -3.402823466e38f;
        #pragma unroll
        for (int i = 0; i < 8; i++) { v[i] = m1 - e[i]; m2 = fmaxf(m2, v[i]); }
        #pragma unroll
        for (int o = 16; o > 0; o >>= 1)
            m2 = fmaxf(m2, __shfl_xor_sync(0xffffffffu, m2, o));

        float p8[8], Ssum = 0.f;
        #pragma unroll
        for (int i = 0; i < 8; i++) { p8[i] = expf(v[i] - m2); Ssum += p8[i]; }
        #pragma unroll
        for (int o = 16; o > 0; o >>= 1)
            Ssum += __shfl_xor_sync(0xffffffffu, Ssum, o);

        float inv = 1.f / Ssum;
        #pragma unroll
        for (int i = 0; i < 8; i++) acc[i] += p8[i] * inv;
    }

    float* out = g_attn + (size_t)gwarp * CHAN + lane * 8;
    *(float4*)&out[0] = make_float4(acc[0], acc[1], acc[2], acc[3]);
    *(float4*)&out[4] = make_float4(acc[4], acc[5], acc[6], acc[7]);
}

// ---------------------------------------------------------------------------
// Kernel 3a: M partials, split-K=4. C_p[kc][b] = conv_w[:,kc*64:+64] @
// attn_b[kc*64:+64,:]. 256 CTAs (one wave), tile 128x128x(K=64).
// ---------------------------------------------------------------------------
__global__ __launch_bounds__(128, 2)
void gemm_m_partial(const float* __restrict__ W)
{
    constexpr int TK = 16, PA = 136, NIT = 4;   // K=64
    __shared__ float As[2][TK * PA];
    __shared__ float Bs[2][TK * 128];

    int id = blockIdx.x;
    int nt = id & 1;
    int mt = (id >> 1) & 1;
    int b  = (id >> 2) & 15;
    int kc = id >> 6;                 // 0..3
    int mBase = mt * 128, nBase = nt * 128, kOff = kc * 64;

    const float* B = g_attn + (size_t)b * (CHAN * CHAN);
    float* O = g_Mp + ((size_t)kc * BATCH + b) * (CHAN * CHAN);

    int tid = threadIdx.x;
    int tx = tid & 15, ty = tid >> 4;

    const float* pA = W + (size_t)(mBase + tid) * CHAN + kOff;
    int krB = tid >> 5, nvB = tid & 31;
    const float* pB = B + (size_t)(kOff + krB) * CHAN + nBase + nvB * 4;

    float4 ra[4], rb[4];
    #pragma unroll
    for (int g = 0; g < 4; g++) {
        ra[g] = *(const float4*)(pA + g * 4);
        rb[g] = *(const float4*)(pB + (size_t)(g * 4) * CHAN);
    }
    {
        float* a = As[0]; float* bsm = Bs[0];
        #pragma unroll
        for (int g = 0; g < 4; g++) {
            a[(g*4+0)*PA + tid] = ra[g].x;  a[(g*4+1)*PA + tid] = ra[g].y;
            a[(g*4+2)*PA + tid] = ra[g].z;  a[(g*4+3)*PA + tid] = ra[g].w;
            *(float4*)&bsm[(krB + g*4) * 128 + nvB * 4] = rb[g];
        }
    }
    pA += TK; pB += (size_t)TK * CHAN;
    #pragma unroll
    for (int g = 0; g < 4; g++) {
        ra[g] = *(const float4*)(pA + g * 4);
        rb[g] = *(const float4*)(pB + (size_t)(g * 4) * CHAN);
    }

    ull acc2[8][8];
    #pragma unroll
    for (int i = 0; i < 8; i++)
        #pragma unroll
        for (int j = 0; j < 8; j++) acc2[i][j] = 0ull;

    for (int ch = 0; ch < NIT; ch++) {
        __syncthreads();
        int cur = ch & 1, nxt = cur ^ 1;
        if (ch + 1 < NIT) {
            float* a = As[nxt]; float* bsm = Bs[nxt];
            #pragma unroll
            for (int g = 0; g < 4; g++) {
                a[(g*4+0)*PA + tid] = ra[g].x;  a[(g*4+1)*PA + tid] = ra[g].y;
                a[(g*4+2)*PA + tid] = ra[g].z;  a[(g*4+3)*PA + tid] = ra[g].w;
                *(float4*)&bsm[(krB + g*4) * 128 + nvB * 4] = rb[g];
            }
        }
        if (ch + 2 < NIT) {
            pA += TK; pB += (size_t)TK * CHAN;
            #pragma unroll
            for (int g = 0; g < 4; g++) {
                ra[g] = *(const float4*)(pA + g * 4);
                rb[g] = *(const float4*)(pB + (size_t)(g * 4) * CHAN);
            }
        }
        const float* a = As[cur]; const float* bsm = Bs[cur];
        #pragma unroll
        for (int k = 0; k < TK; k++) {
            ulonglong2 q0 = *(const ulonglong2*)&a[k*PA + ty*16];
            ulonglong2 q1 = *(const ulonglong2*)&a[k*PA + ty*16 + 4];
            ulonglong2 q2 = *(const ulonglong2*)&a[k*PA + ty*16 + 8];
            ulonglong2 q3 = *(const ulonglong2*)&a[k*PA + ty*16 + 12];
            ull aa[8] = {q0.x, q0.y, q1.x, q1.y, q2.x, q2.y, q3.x, q3.y};
            float4 b0 = *(const float4*)&bsm[k*128 + tx*4];
            float4 b1 = *(const float4*)&bsm[k*128 + 64 + tx*4];
            ull bb[8] = {bcast2(b0.x), bcast2(b0.y), bcast2(b0.z), bcast2(b0.w),
                         bcast2(b1.x), bcast2(b1.y), bcast2(b1.z), bcast2(b1.w)};
            #pragma unroll
            for (int i = 0; i < 8; i++)
                #pragma unroll
                for (int j = 0; j < 8; j++)
                    fma2(acc2[i][j], aa[i], bb[j]);
        }
    }

    #pragma unroll
    for (int r = 0; r < 16; r++) {
        int row = mBase + ty * 16 + r;
        size_t base = (size_t)row * CHAN + nBase + tx*4;
        float v[8];
        #pragma unroll
        for (int n = 0; n < 8; n++) {
            float2 u = unpack2(acc2[r >> 1][n]);
            v[n] = (r & 1) ? u.y : u.x;
        }
        *(float4*)&O[base]      = make_float4(v[0], v[1], v[2], v[3]);
        *(float4*)&O[base + 64] = make_float4(v[4], v[5], v[6], v[7]);
    }
}

// ---------------------------------------------------------------------------
// Kernel 3b: g_M = gamma * sum of 4 M-partials (streaming).
// ---------------------------------------------------------------------------
__global__ __launch_bounds__(256)
void reduce_m_kernel(const float* __restrict__ gamma_p)
{
    const size_t nVec = (size_t)BATCH * CHAN * CHAN / 4;
    const float4* in  = (const float4*)g_Mp;
    float4* out = (float4*)g_M;
    float gamma = gamma_p[0];
    size_t step = (size_t)gridDim.x * blockDim.x;
    for (size_t i = (size_t)blockIdx.x * blockDim.x + threadIdx.x;
         i < nVec; i += step) {
        float4 a0 = in[i];
        float4 a1 = in[nVec + i];
        float4 a2 = in[2 * nVec + i];
        float4 a3 = in[3 * nVec + i];
        out[i] = make_float4(gamma * (a0.x + a1.x + a2.x + a3.x),
                             gamma * (a0.y + a1.y + a2.y + a3.y),
                             gamma * (a0.z + a1.z + a2.z + a3.z),
                             gamma * (a0.w + a1.w + a2.w + a3.w));
    }
}

// ---------------------------------------------------------------------------
// Kernel 4: final TN GEMM, out = M_b @ x_b + gamma*bias + x. K=256,
// block tile 128x128x16, 128 threads, 16x8 micro-tile.
// ---------------------------------------------------------------------------
__global__ __launch_bounds__(128, 2)
void gemm_final(const float* __restrict__ Mb,
                const float* __restrict__ X,
                float* __restrict__ Ob,
                const float* __restrict__ bias,
                const float* __restrict__ gamma_p)
{
    constexpr int TK = 16, Kdim = 256, PA = 136, NIT = 16, NCOLS = NPIX;
    __shared__ float As[2][TK * PA];
    __shared__ float Bs[2][TK * 128];

    int id = blockIdx.x;
    int nt = id % 32; id /= 32;
    int mt = id & 1;
    int b  = id >> 1;
    int mBase = mt * 128, nBase = nt * 128;

    const float* A = Mb + (size_t)b * (CHAN * CHAN);
    const float* B = X + (size_t)b * ((size_t)CHAN * NCOLS);
    float* O = Ob + (size_t)b * ((size_t)CHAN * NCOLS);
    const float* R = B;

    int tid = threadIdx.x;
    int tx = tid & 15, ty = tid >> 4;

    const float* pA = A + (size_t)(mBase + tid) * Kdim;
    int krB = tid >> 5, nvB = tid & 31;
    const float* pB = B + (size_t)krB * NCOLS + nBase + nvB * 4;

    float4 ra[4], rb[4];
    #pragma unroll
    for (int g = 0; g < 4; g++) {
        ra[g] = *(const float4*)(pA + g * 4);
        rb[g] = *(const float4*)(pB + (size_t)(g * 4) * NCOLS);
    }
    {
        float* a = As[0]; float* bsm = Bs[0];
        #pragma unroll
        for (int g = 0; g < 4; g++) {
            a[(g*4+0)*PA + tid] = ra[g].x;  a[(g*4+1)*PA + tid] = ra[g].y;
            a[(g*4+2)*PA + tid] = ra[g].z;  a[(g*4+3)*PA + tid] = ra[g].w;
            *(float4*)&bsm[(krB + g*4) * 128 + nvB * 4] = rb[g];
        }
    }
    pA += TK; pB += (size_t)TK * NCOLS;
    #pragma unroll
    for (int g = 0; g < 4; g++) {
        ra[g] = *(const float4*)(pA + g * 4);
        rb[g] = *(const float4*)(pB + (size_t)(g * 4) * NCOLS);
    }

    ull acc2[8][8];
    #pragma unroll
    for (int i = 0; i < 8; i++)
        #pragma unroll
        for (int j = 0; j < 8; j++) acc2[i][j] = 0ull;

    for (int ch = 0; ch < NIT; ch++) {
        __syncthreads();
        int cur = ch & 1, nxt = cur ^ 1;

        if (ch + 1 < NIT) {
            float* a = As[nxt]; float* bsm = Bs[nxt];
            #pragma unroll
            for (int g = 0; g < 4; g++) {
                a[(g*4+0)*PA + tid] = ra[g].x;  a[(g*4+1)*PA + tid] = ra[g].y;
                a[(g*4+2)*PA + tid] = ra[g].z;  a[(g*4+3)*PA + tid] = ra[g].w;
                *(float4*)&bsm[(krB + g*4) * 128 + nvB * 4] = rb[g];
            }
        }
        if (ch + 2 < NIT) {
            pA += TK; pB += (size_t)TK * NCOLS;
            #pragma unroll
            for (int g = 0; g < 4; g++) {
                ra[g] = *(const float4*)(pA + g * 4);
                rb[g] = *(const float4*)(pB + (size_t)(g * 4) * NCOLS);
            }
        }

        const float* a = As[cur]; const float* bsm = Bs[cur];
        #pragma unroll
        for (int k = 0; k < TK; k++) {
            ulonglong2 q0 = *(const ulonglong2*)&a[k*PA + ty*16];
            ulonglong2 q1 = *(const ulonglong2*)&a[k*PA + ty*16 + 4];
            ulonglong2 q2 = *(const ulonglong2*)&a[k*PA + ty*16 + 8];
            ulonglong2 q3 = *(const ulonglong2*)&a[k*PA + ty*16 + 12];
            ull aa[8] = {q0.x, q0.y, q1.x, q1.y, q2.x, q2.y, q3.x, q3.y};
            float4 b0 = *(const float4*)&bsm[k*128 + tx*4];
            float4 b1 = *(const float4*)&bsm[k*128 + 64 + tx*4];
            ull bb[8] = {bcast2(b0.x), bcast2(b0.y), bcast2(b0.z), bcast2(b0.w),
                         bcast2(b1.x), bcast2(b1.y), bcast2(b1.z), bcast2(b1.w)};
            #pragma unroll
            for (int i = 0; i < 8; i++)
                #pragma unroll
                for (int j = 0; j < 8; j++)
                    fma2(acc2[i][j], aa[i], bb[j]);
        }
    }

    float gamma = gamma_p[0];
    #pragma unroll
    for (int r = 0; r < 16; r++) {
        int row = mBase + ty * 16 + r;
        size_t base = (size_t)row * NCOLS + nBase + tx*4;
        float v[8];
        #pragma unroll
        for (int n = 0; n < 8; n++) {
            float2 u = unpack2(acc2[r >> 1][n]);
            v[n] = (r & 1) ? u.y : u.x;
        }
        float gb = gamma * bias[row];
        float4 r0 = *(const float4*)&R[base];
        float4 r1 = *(const float4*)&R[base + 64];
        *(float4*)&O[base] = make_float4(
            v[0] + gb + r0.x, v[1] + gb + r0.y,
            v[2] + gb + r0.z, v[3] + gb + r0.w);
        *(float4*)&O[base + 64] = make_float4(
            v[4] + gb + r1.x, v[5] + gb + r1.y,
            v[6] + gb + r1.z, v[7] + gb + r1.w);
    }
}

// ---------------------------------------------------------------------------
extern "C" void kernel_launch(void* const* d_in, const int* in_sizes, int n_in,
                              void* d_out, int out_size)
{
    const float* x      = (const float*)d_in[0];
    const float* y      = (const float*)d_in[1];
    const float* z      = (const float*)d_in[2];
    const float* conv_w = (const float*)d_in[3];
    const float* conv_b = (const float*)d_in[4];
    const float* gamma  = (const float*)d_in[5];
    float* out = (float*)d_out;

    // resolve device addresses of __device__ globals (host shadows are NOT
    // valid device pointers — R15's bug)
    float* pM = nullptr;
    cudaGetSymbolAddress((void**)&pM, g_M);

    // 1) three energy GEMMs, split-K=5 uneven: 960 CTAs (80 exit early)
    energy_kernel<<<3 * BATCH * 4 * KSPLIT, 128>>>(x, y, z);
    // 2) softmax + sum over sources (reads 5 partials directly)
    softmax_sum_kernel<<<BATCH * CHAN / 8, 256>>>();
    // 3a) M partials: split-K=4, 256 CTAs (one wave)
    gemm_m_partial<<<4 * BATCH * 4, 128>>>(conv_w);
    // 3b) g_M = gamma * sum partials
    reduce_m_kernel<<<256, 256>>>(gamma);
    // 4) out = M_b @ x_b + gamma*conv_b + x  (1024 CTAs)
    gemm_final<<<BATCH * 2 * 32, 128>>>(pM, x, out, conv_b, gamma);
}

// round 17
// speedup vs baseline: 1.1412x; 1.0610x over previous
#include <cuda_runtime.h>
#include <math.h>
#include <stdint.h>

#define BATCH 16
#define CHAN  256
#define NPIX  4096
#define KSPLIT 5                 // uneven: 832 + 4x816

typedef unsigned long long ull;

// Scratch (allocation-free: __device__ globals)
__device__ float g_epart[(size_t)KSPLIT * 3 * BATCH * CHAN * CHAN];  // 63 MB
__device__ float g_attn[(unsigned)BATCH * CHAN * CHAN];
__device__ float g_Mp[4u * BATCH * CHAN * CHAN];                     // M partials
__device__ float g_M[(unsigned)BATCH * CHAN * CHAN];

#define EPART_STRIDE ((size_t)3 * BATCH * CHAN * CHAN)

// ---- packed f32x2 helpers (FFMA2 kernels) -----------------------------------
__device__ __forceinline__ ull bcast2(float v) {
    ull r; asm("mov.b64 %0, {%1, %1};" : "=l"(r) : "f"(v)); return r;
}
__device__ __forceinline__ void fma2(ull& d, ull a, ull b) {
    asm("fma.rn.f32x2 %0, %1, %2, %0;" : "+l"(d) : "l"(a), "l"(b));
}
__device__ __forceinline__ float2 unpack2(ull v) {
    float2 r; asm("mov.b64 {%0, %1}, %2;" : "=f"(r.x), "=f"(r.y) : "l"(v)); return r;
}

// ---- tensor-core helpers (base PTX, no 'a'-gated features) -------------------
__device__ __forceinline__ void split_tf32(float v, uint32_t& hi, uint32_t& lo) {
    asm("cvt.rna.tf32.f32 %0, %1;" : "=r"(hi) : "f"(v));
    float r = v - __uint_as_float(hi);
    asm("cvt.rna.tf32.f32 %0, %1;" : "=r"(lo) : "f"(r));
}
// D += A(16x8, tf32, row) * B(8x8, tf32, col), fp32 accumulate
__device__ __forceinline__ void mma_tf32(float4& d, const uint4& a, const uint2& b) {
    asm volatile(
        "mma.sync.aligned.m16n8k8.row.col.f32.tf32.tf32.f32 "
        "{%0,%1,%2,%3}, {%4,%5,%6,%7}, {%8,%9}, {%0,%1,%2,%3};"
        : "+f"(d.x), "+f"(d.y), "+f"(d.z), "+f"(d.w)
        : "r"(a.x), "r"(a.y), "r"(a.z), "r"(a.w), "r"(b.x), "r"(b.y));
}

// ---------------------------------------------------------------------------
// Kernel 1: partial energy via mma.sync TF32 3x-split. Split-K=5 (uneven).
// Block tile 128x128x16, 128 threads = 4 warps in 2x2 (each warp 64x64).
// Raw fp32 tiles staged row-major (PAD=20: conflict-free STS.128 + frag LDS),
// hi/lo tf32 split in registers, fp32 mma accumulate.
// s=0 (x@x^T) symmetric: tile (1,0) skipped, tile (0,1) writes its mirror.
// ---------------------------------------------------------------------------
__global__ __launch_bounds__(128, 2)
void energy_tensor_kernel(const float* __restrict__ x, const float* __restrict__ y,
                          const float* __restrict__ z)
{
    constexpr int TK = 16, PAD = 20;
    __shared__ float As[2][128 * PAD];
    __shared__ float Bsm[2][128 * PAD];

    int id = blockIdx.x;
    int t  = id & 3;
    int r5 = id >> 2;
    int kchunk = r5 % 5;
    int bs     = r5 / 5;
    int b  = bs & 15;
    int s  = bs >> 4;
    if (s == 0 && t == 2) return;           // symmetric: mirror of tile (0,1)
    int cBase = (t >> 1) * 128;
    int dBase = (t & 1) * 128;
    int kStart = kchunk ? (16 + 816 * kchunk) : 0;
    int NIT    = kchunk ? 51 : 52;          // chunk len / 16

    const float* A = x + (size_t)b * (CHAN * NPIX);
    const float* S = (s == 0 ? x : (s == 1 ? y : z)) + (size_t)b * (CHAN * NPIX);

    int tid  = threadIdx.x;
    int lane = tid & 31;
    int w    = tid >> 5;
    int wm   = w >> 1, wn = w & 1;
    int lr   = lane >> 2;      // fragment row group 0..7
    int lc   = lane & 3;       // fragment col group 0..3

    const float* pA = A + (size_t)(cBase + tid) * NPIX + kStart;
    const float* pB = S + (size_t)(dBase + tid) * NPIX + kStart;

    float4 ra[4], rb[4];
    #pragma unroll
    for (int g = 0; g < 4; g++) {
        ra[g] = *(const float4*)(pA + g * 4);
        rb[g] = *(const float4*)(pB + g * 4);
    }
    {   // chunk 0 -> buf 0 (row-major, STS.128 conflict-free with PAD=20)
        #pragma unroll
        for (int g = 0; g < 4; g++) {
            *(float4*)&As[0][tid * PAD + g * 4]  = ra[g];
            *(float4*)&Bsm[0][tid * PAD + g * 4] = rb[g];
        }
    }
    pA += TK; pB += TK;
    #pragma unroll
    for (int g = 0; g < 4; g++) {
        ra[g] = *(const float4*)(pA + g * 4);
        rb[g] = *(const float4*)(pB + g * 4);
    }

    // acc[mti][nti]: 16x8 fp32 fragment (c0,c1,c2,c3) = (x,y,z,w)
    float4 acc[4][8];
    #pragma unroll
    for (int i = 0; i < 4; i++)
        #pragma unroll
        for (int j = 0; j < 8; j++) acc[i][j] = make_float4(0.f, 0.f, 0.f, 0.f);

    for (int ch = 0; ch < NIT; ch++) {
        __syncthreads();
        int cur = ch & 1, nxt = cur ^ 1;

        if (ch + 1 < NIT) {
            #pragma unroll
            for (int g = 0; g < 4; g++) {
                *(float4*)&As[nxt][tid * PAD + g * 4]  = ra[g];
                *(float4*)&Bsm[nxt][tid * PAD + g * 4] = rb[g];
            }
        }
        if (ch + 2 < NIT) {
            pA += TK; pB += TK;
            #pragma unroll
            for (int g = 0; g < 4; g++) {
                ra[g] = *(const float4*)(pA + g * 4);
                rb[g] = *(const float4*)(pB + g * 4);
            }
        }

        const float* a   = As[cur];
        const float* bsm = Bsm[cur];
        #pragma unroll
        for (int kg = 0; kg < 2; kg++) {
            // A fragments for this warp's 4 m16-tiles, split hi/lo
            uint4 Ahi[4], Alo[4];
            #pragma unroll
            for (int mti = 0; mti < 4; mti++) {
                int r0 = wm * 64 + mti * 16 + lr;
                const float* base = &a[r0 * PAD + kg * 8 + lc];
                float v0 = base[0];
                float v1 = base[8 * PAD];
                float v2 = base[4];
                float v3 = base[8 * PAD + 4];
                split_tf32(v0, Ahi[mti].x, Alo[mti].x);
                split_tf32(v1, Ahi[mti].y, Alo[mti].y);
                split_tf32(v2, Ahi[mti].z, Alo[mti].z);
                split_tf32(v3, Ahi[mti].w, Alo[mti].w);
            }
            #pragma unroll
            for (int nti = 0; nti < 8; nti++) {
                int r0 = wn * 64 + nti * 8 + lr;    // B rows are d-cols
                const float* base = &bsm[r0 * PAD + kg * 8 + lc];
                float v0 = base[0];
                float v1 = base[4];
                uint2 Bhi, Blo;
                split_tf32(v0, Bhi.x, Blo.x);
                split_tf32(v1, Bhi.y, Blo.y);
                #pragma unroll
                for (int mti = 0; mti < 4; mti++) {
                    mma_tf32(acc[mti][nti], Ahi[mti], Bhi);
                    mma_tf32(acc[mti][nti], Ahi[mti], Blo);
                    mma_tf32(acc[mti][nti], Alo[mti], Bhi);
                }
            }
        }
    }

    float* E = g_epart + (size_t)kchunk * EPART_STRIDE +
               ((size_t)s * BATCH + b) * (CHAN * CHAN);
    #pragma unroll
    for (int mti = 0; mti < 4; mti++) {
        #pragma unroll
        for (int nti = 0; nti < 8; nti++) {
            int row = cBase + wm * 64 + mti * 16 + lr;
            int col = dBase + wn * 64 + nti * 8 + lc * 2;
            float4 d = acc[mti][nti];
            *(float2*)&E[(size_t)row * CHAN + col]       = make_float2(d.x, d.y);
            *(float2*)&E[(size_t)(row + 8) * CHAN + col] = make_float2(d.z, d.w);
        }
    }

    if (s == 0 && t == 1) {   // mirror write (symmetric x@x^T)
        #pragma unroll
        for (int mti = 0; mti < 4; mti++) {
            #pragma unroll
            for (int nti = 0; nti < 8; nti++) {
                int row = cBase + wm * 64 + mti * 16 + lr;
                int col = dBase + wn * 64 + nti * 8 + lc * 2;
                float4 d = acc[mti][nti];
                E[(size_t)col * CHAN + row]           = d.x;
                E[(size_t)(col + 1) * CHAN + row]     = d.y;
                E[(size_t)col * CHAN + row + 8]       = d.z;
                E[(size_t)(col + 1) * CHAN + row + 8] = d.w;
            }
        }
    }
}

// ---------------------------------------------------------------------------
// Kernel 2: attn[b][c][:] = sum_s softmax(rowmax(E_s) - E_s); E_s = sum of
// 5 partials, read directly. One warp per (b,c) row.
// ---------------------------------------------------------------------------
__global__ __launch_bounds__(256)
void softmax_sum_kernel()
{
    int gwarp = (blockIdx.x * blockDim.x + threadIdx.x) >> 5;
    int lane  = threadIdx.x & 31;

    float acc[8];
    #pragma unroll
    for (int i = 0; i < 8; i++) acc[i] = 0.f;

    #pragma unroll
    for (int s = 0; s < 3; s++) {
        float e[8];
        #pragma unroll
        for (int i = 0; i < 8; i++) e[i] = 0.f;
        #pragma unroll
        for (int p = 0; p < KSPLIT; p++) {
            const float* row = g_epart + (size_t)p * EPART_STRIDE +
                ((size_t)s * BATCH * CHAN + gwarp) * CHAN;
            float4 e0 = *(const float4*)&row[lane * 8];
            float4 e1 = *(const float4*)&row[lane * 8 + 4];
            e[0] += e0.x; e[1] += e0.y; e[2] += e0.z; e[3] += e0.w;
            e[4] += e1.x; e[5] += e1.y; e[6] += e1.z; e[7] += e1.w;
        }

        float m1 = e[0];
        #pragma unroll
        for (int i = 1; i < 8; i++) m1 = fmaxf(m1, e[i]);
        #pragma unroll
        for (int o = 16; o > 0; o >>= 1)
            m1 = fmaxf(m1, __shfl_xor_sync(0xffffffffu, m1, o));

        float v[8], m2 = -3.402823466e38f;
        #pragma unroll
        for (int i = 0; i < 8; i++) { v[i] = m1 - e[i]; m2 = fmaxf(m2, v[i]); }
        #pragma unroll
        for (int o = 16; o > 0; o >>= 1)
            m2 = fmaxf(m2, __shfl_xor_sync(0xffffffffu, m2, o));

        float p8[8], Ssum = 0.f;
        #pragma unroll
        for (int i = 0; i < 8; i++) { p8[i] = expf(v[i] - m2); Ssum += p8[i]; }
        #pragma unroll
        for (int o = 16; o > 0; o >>= 1)
            Ssum += __shfl_xor_sync(0xffffffffu, Ssum, o);

        float inv = 1.f / Ssum;
        #pragma unroll
        for (int i = 0; i < 8; i++) acc[i] += p8[i] * inv;
    }

    float* out = g_attn + (size_t)gwarp * CHAN + lane * 8;
    *(float4*)&out[0] = make_float4(acc[0], acc[1], acc[2], acc[3]);
    *(float4*)&out[4] = make_float4(acc[4], acc[5], acc[6], acc[7]);
}

// ---------------------------------------------------------------------------
// Kernel 3a: M partials, split-K=4 (FFMA2 path, one full wave).
// ---------------------------------------------------------------------------
__global__ __launch_bounds__(128, 2)
void gemm_m_partial(const float* __restrict__ W)
{
    constexpr int TK = 16, PA = 136, NIT = 4;   // K=64
    __shared__ float As[2][TK * PA];
    __shared__ float Bs[2][TK * 128];

    int id = blockIdx.x;
    int nt = id & 1;
    int mt = (id >> 1) & 1;
    int b  = (id >> 2) & 15;
    int kc = id >> 6;                 // 0..3
    int mBase = mt * 128, nBase = nt * 128, kOff = kc * 64;

    const float* B = g_attn + (size_t)b * (CHAN * CHAN);
    float* O = g_Mp + ((size_t)kc * BATCH + b) * (CHAN * CHAN);

    int tid = threadIdx.x;
    int tx = tid & 15, ty = tid >> 4;

    const float* pA = W + (size_t)(mBase + tid) * CHAN + kOff;
    int krB = tid >> 5, nvB = tid & 31;
    const float* pB = B + (size_t)(kOff + krB) * CHAN + nBase + nvB * 4;

    float4 ra[4], rb[4];
    #pragma unroll
    for (int g = 0; g < 4; g++) {
        ra[g] = *(const float4*)(pA + g * 4);
        rb[g] = *(const float4*)(pB + (size_t)(g * 4) * CHAN);
    }
    {
        float* a = As[0]; float* bsm = Bs[0];
        #pragma unroll
        for (int g = 0; g < 4; g++) {
            a[(g*4+0)*PA + tid] = ra[g].x;  a[(g*4+1)*PA + tid] = ra[g].y;
            a[(g*4+2)*PA + tid] = ra[g].z;  a[(g*4+3)*PA + tid] = ra[g].w;
            *(float4*)&bsm[(krB + g*4) * 128 + nvB * 4] = rb[g];
        }
    }
    pA += TK; pB += (size_t)TK * CHAN;
    #pragma unroll
    for (int g = 0; g < 4; g++) {
        ra[g] = *(const float4*)(pA + g * 4);
        rb[g] = *(const float4*)(pB + (size_t)(g * 4) * CHAN);
    }

    ull acc2[8][8];
    #pragma unroll
    for (int i = 0; i < 8; i++)
        #pragma unroll
        for (int j = 0; j < 8; j++) acc2[i][j] = 0ull;

    for (int ch = 0; ch < NIT; ch++) {
        __syncthreads();
        int cur = ch & 1, nxt = cur ^ 1;
        if (ch + 1 < NIT) {
            float* a = As[nxt]; float* bsm = Bs[nxt];
            #pragma unroll
            for (int g = 0; g < 4; g++) {
                a[(g*4+0)*PA + tid] = ra[g].x;  a[(g*4+1)*PA + tid] = ra[g].y;
                a[(g*4+2)*PA + tid] = ra[g].z;  a[(g*4+3)*PA + tid] = ra[g].w;
                *(float4*)&bsm[(krB + g*4) * 128 + nvB * 4] = rb[g];
            }
        }
        if (ch + 2 < NIT) {
            pA += TK; pB += (size_t)TK * CHAN;
            #pragma unroll
            for (int g = 0; g < 4; g++) {
                ra[g] = *(const float4*)(pA + g * 4);
                rb[g] = *(const float4*)(pB + (size_t)(g * 4) * CHAN);
            }
        }
        const float* a = As[cur]; const float* bsm = Bs[cur];
        #pragma unroll
        for (int k = 0; k < TK; k++) {
            ulonglong2 q0 = *(const ulonglong2*)&a[k*PA + ty*16];
            ulonglong2 q1 = *(const ulonglong2*)&a[k*PA + ty*16 + 4];
            ulonglong2 q2 = *(const ulonglong2*)&a[k*PA + ty*16 + 8];
            ulonglong2 q3 = *(const ulonglong2*)&a[k*PA + ty*16 + 12];
            ull aa[8] = {q0.x, q0.y, q1.x, q1.y, q2.x, q2.y, q3.x, q3.y};
            float4 b0 = *(const float4*)&bsm[k*128 + tx*4];
            float4 b1 = *(const float4*)&bsm[k*128 + 64 + tx*4];
            ull bb[8] = {bcast2(b0.x), bcast2(b0.y), bcast2(b0.z), bcast2(b0.w),
                         bcast2(b1.x), bcast2(b1.y), bcast2(b1.z), bcast2(b1.w)};
            #pragma unroll
            for (int i = 0; i < 8; i++)
                #pragma unroll
                for (int j = 0; j < 8; j++)
                    fma2(acc2[i][j], aa[i], bb[j]);
        }
    }

    #pragma unroll
    for (int r = 0; r < 16; r++) {
        int row = mBase + ty * 16 + r;
        size_t base = (size_t)row * CHAN + nBase + tx*4;
        float v[8];
        #pragma unroll
        for (int n = 0; n < 8; n++) {
            float2 u = unpack2(acc2[r >> 1][n]);
            v[n] = (r & 1) ? u.y : u.x;
        }
        *(float4*)&O[base]      = make_float4(v[0], v[1], v[2], v[3]);
        *(float4*)&O[base + 64] = make_float4(v[4], v[5], v[6], v[7]);
    }
}

// ---------------------------------------------------------------------------
// Kernel 3b: g_M = gamma * sum of 4 M-partials (streaming).
// ---------------------------------------------------------------------------
__global__ __launch_bounds__(256)
void reduce_m_kernel(const float* __restrict__ gamma_p)
{
    const size_t nVec = (size_t)BATCH * CHAN * CHAN / 4;
    const float4* in  = (const float4*)g_Mp;
    float4* out = (float4*)g_M;
    float gamma = gamma_p[0];
    size_t step = (size_t)gridDim.x * blockDim.x;
    for (size_t i = (size_t)blockIdx.x * blockDim.x + threadIdx.x;
         i < nVec; i += step) {
        float4 a0 = in[i];
        float4 a1 = in[nVec + i];
        float4 a2 = in[2 * nVec + i];
        float4 a3 = in[3 * nVec + i];
        out[i] = make_float4(gamma * (a0.x + a1.x + a2.x + a3.x),
                             gamma * (a0.y + a1.y + a2.y + a3.y),
                             gamma * (a0.z + a1.z + a2.z + a3.z),
                             gamma * (a0.w + a1.w + a2.w + a3.w));
    }
}

// ---------------------------------------------------------------------------
// Kernel 4: final TN GEMM, out = M_b @ x_b + gamma*bias + x. (FFMA2 path)
// ---------------------------------------------------------------------------
__global__ __launch_bounds__(128, 2)
void gemm_final(const float* __restrict__ Mb,
                const float* __restrict__ X,
                float* __restrict__ Ob,
                const float* __restrict__ bias,
                const float* __restrict__ gamma_p)
{
    constexpr int TK = 16, Kdim = 256, PA = 136, NIT = 16, NCOLS = NPIX;
    __shared__ float As[2][TK * PA];
    __shared__ float Bs[2][TK * 128];

    int id = blockIdx.x;
    int nt = id % 32; id /= 32;
    int mt = id & 1;
    int b  = id >> 1;
    int mBase = mt * 128, nBase = nt * 128;

    const float* A = Mb + (size_t)b * (CHAN * CHAN);
    const float* B = X + (size_t)b * ((size_t)CHAN * NCOLS);
    float* O = Ob + (size_t)b * ((size_t)CHAN * NCOLS);
    const float* R = B;

    int tid = threadIdx.x;
    int tx = tid & 15, ty = tid >> 4;

    const float* pA = A + (size_t)(mBase + tid) * Kdim;
    int krB = tid >> 5, nvB = tid & 31;
    const float* pB = B + (size_t)krB * NCOLS + nBase + nvB * 4;

    float4 ra[4], rb[4];
    #pragma unroll
    for (int g = 0; g < 4; g++) {
        ra[g] = *(const float4*)(pA + g * 4);
        rb[g] = *(const float4*)(pB + (size_t)(g * 4) * NCOLS);
    }
    {
        float* a = As[0]; float* bsm = Bs[0];
        #pragma unroll
        for (int g = 0; g < 4; g++) {
            a[(g*4+0)*PA + tid] = ra[g].x;  a[(g*4+1)*PA + tid] = ra[g].y;
            a[(g*4+2)*PA + tid] = ra[g].z;  a[(g*4+3)*PA + tid] = ra[g].w;
            *(float4*)&bsm[(krB + g*4) * 128 + nvB * 4] = rb[g];
        }
    }
    pA += TK; pB += (size_t)TK * NCOLS;
    #pragma unroll
    for (int g = 0; g < 4; g++) {
        ra[g] = *(const float4*)(pA + g * 4);
        rb[g] = *(const float4*)(pB + (size_t)(g * 4) * NCOLS);
    }

    ull acc2[8][8];
    #pragma unroll
    for (int i = 0; i < 8; i++)
        #pragma unroll
        for (int j = 0; j < 8; j++) acc2[i][j] = 0ull;

    for (int ch = 0; ch < NIT; ch++) {
        __syncthreads();
        int cur = ch & 1, nxt = cur ^ 1;

        if (ch + 1 < NIT) {
            float* a = As[nxt]; float* bsm = Bs[nxt];
            #pragma unroll
            for (int g = 0; g < 4; g++) {
                a[(g*4+0)*PA + tid] = ra[g].x;  a[(g*4+1)*PA + tid] = ra[g].y;
                a[(g*4+2)*PA + tid] = ra[g].z;  a[(g*4+3)*PA + tid] = ra[g].w;
                *(float4*)&bsm[(krB + g*4) * 128 + nvB * 4] = rb[g];
            }
        }
        if (ch + 2 < NIT) {
            pA += TK; pB += (size_t)TK * NCOLS;
            #pragma unroll
            for (int g = 0; g < 4; g++) {
                ra[g] = *(const float4*)(pA + g * 4);
                rb[g] = *(const float4*)(pB + (size_t)(g * 4) * NCOLS);
            }
        }

        const float* a = As[cur]; const float* bsm = Bs[cur];
        #pragma unroll
        for (int k = 0; k < TK; k++) {
            ulonglong2 q0 = *(const ulonglong2*)&a[k*PA + ty*16];
            ulonglong2 q1 = *(const ulonglong2*)&a[k*PA + ty*16 + 4];
            ulonglong2 q2 = *(const ulonglong2*)&a[k*PA + ty*16 + 8];
            ulonglong2 q3 = *(const ulonglong2*)&a[k*PA + ty*16 + 12];
            ull aa[8] = {q0.x, q0.y, q1.x, q1.y, q2.x, q2.y, q3.x, q3.y};
            float4 b0 = *(const float4*)&bsm[k*128 + tx*4];
            float4 b1 = *(const float4*)&bsm[k*128 + 64 + tx*4];
            ull bb[8] = {bcast2(b0.x), bcast2(b0.y), bcast2(b0.z), bcast2(b0.w),
                         bcast2(b1.x), bcast2(b1.y), bcast2(b1.z), bcast2(b1.w)};
            #pragma unroll
            for (int i = 0; i < 8; i++)
                #pragma unroll
                for (int j = 0; j < 8; j++)
                    fma2(acc2[i][j], aa[i], bb[j]);
        }
    }

    float gamma = gamma_p[0];
    #pragma unroll
    for (int r = 0; r < 16; r++) {
        int row = mBase + ty * 16 + r;
        size_t base = (size_t)row * NCOLS + nBase + tx*4;
        float v[8];
        #pragma unroll
        for (int n = 0; n < 8; n++) {
            float2 u = unpack2(acc2[r >> 1][n]);
            v[n] = (r & 1) ? u.y : u.x;
        }
        float gb = gamma * bias[row];
        float4 r0 = *(const float4*)&R[base];
        float4 r1 = *(const float4*)&R[base + 64];
        *(float4*)&O[base] = make_float4(
            v[0] + gb + r0.x, v[1] + gb + r0.y,
            v[2] + gb + r0.z, v[3] + gb + r0.w);
        *(float4*)&O[base + 64] = make_float4(
            v[4] + gb + r1.x, v[5] + gb + r1.y,
            v[6] + gb + r1.z, v[7] + gb + r1.w);
    }
}

// ---------------------------------------------------------------------------
extern "C" void kernel_launch(void* const* d_in, const int* in_sizes, int n_in,
                              void* d_out, int out_size)
{
    const float* x      = (const float*)d_in[0];
    const float* y      = (const float*)d_in[1];
    const float* z      = (const float*)d_in[2];
    const float* conv_w = (const float*)d_in[3];
    const float* conv_b = (const float*)d_in[4];
    const float* gamma  = (const float*)d_in[5];
    float* out = (float*)d_out;

    // device address of g_M (host shadow is NOT a device pointer)
    float* pM = nullptr;
    cudaGetSymbolAddress((void**)&pM, g_M);

    // 1) three energy GEMMs via tensor-core TF32 3x-split: 960 CTAs
    energy_tensor_kernel<<<3 * BATCH * 4 * KSPLIT, 128>>>(x, y, z);
    // 2) softmax + sum over sources (reads 5 partials directly)
    softmax_sum_kernel<<<BATCH * CHAN / 8, 256>>>();
    // 3a) M partials: split-K=4, 256 CTAs (one wave)
    gemm_m_partial<<<4 * BATCH * 4, 128>>>(conv_w);
    // 3b) g_M = gamma * sum partials
    reduce_m_kernel<<<256, 256>>>(gamma);
    // 4) out = M_b @ x_b + gamma*conv_b + x  (1024 CTAs)
    gemm_final<<<BATCH * 2 * 32, 128>>>(pM, x, out, conv_b, gamma);
}